// round 6
// baseline (speedup 1.0000x reference)
#include <cuda_runtime.h>

#define NQ    14
#define DEPTH 6
#define DIM   16384
#define TPB   1024     // 10 thread bits
#define AMPS  16       // 4 local bits

#define BUFN  17408    // h(16383)=17405 -> padded state buffer (ull)

typedef unsigned long long ull;

// ---------- packed f32x2 helpers ----------
__device__ __forceinline__ ull pack2(float x, float y){
    ull r; asm("mov.b64 %0,{%1,%2};" : "=l"(r) : "f"(x), "f"(y)); return r;
}
__device__ __forceinline__ void unpack2(ull v, float& x, float& y){
    asm("mov.b64 {%0,%1},%2;" : "=f"(x), "=f"(y) : "l"(v));
}
__device__ __forceinline__ ull f2fma(ull a, ull b, ull c){
    ull d; asm("fma.rn.f32x2 %0,%1,%2,%3;" : "=l"(d) : "l"(a), "l"(b), "l"(c)); return d;
}

// RY gate on register-local bit K (K=0..3) via Paeth 3-shear:
//   lo -= T*hi ; hi += S*lo ; lo -= T*hi   (T = tan(phi/2), S = sin(phi))
template<int K>
__device__ __forceinline__ void gate(ull* a, ull nT, ull S){
#pragma unroll
    for (int m = 0; m < 8; m++){
        int lo = ((m >> K) << (K + 1)) | (m & ((1 << K) - 1));
        int hi = lo | (1 << K);
        ull a0 = a[lo], a1 = a[hi];
        a0 = f2fma(nT, a1, a0);
        a1 = f2fma(S,  a0, a1);
        a0 = f2fma(nT, a1, a0);
        a[lo] = a0; a[hi] = a1;
    }
}

// ---------- layouts (phys index i, smem slot h(i) = i + 2*(i>>5)) ----------
// A: local = phys 0-3  : i = (t<<4) | l                  slot = baseA + l
// B: local = phys 4-7  : i = w<<9 | L4<<8 | l<<4 | Llow  slot = baseB + 16l + 2*(l>>1)
// C: local = phys 8-11 : i = wHi<<12 | l<<8 | wLo<<5 | L slot = baseC + 272l
// D: local = phys 10-13: i = (l<<10) | t                 slot = baseD + 1088l
// (w = t>>5 carries phys 9-13 in A/B; L = t&31)

__device__ __forceinline__ void applyCZ(ull* amp, unsigned mask){
#pragma unroll
    for (int l = 0; l < AMPS; l++){
        if ((mask >> l) & 1u)
            amp[l] ^= 0x8000000080000000ULL;
    }
}

#define ST_A(p,a) do{ _Pragma("unroll") for(int l=0;l<AMPS;l++) (p)[l] = (a)[l]; }while(0)
#define LD_A(p,a) do{ _Pragma("unroll") for(int l=0;l<AMPS;l++) (a)[l] = (p)[l]; }while(0)
#define ST_B(p,a) do{ _Pragma("unroll") for(int l=0;l<AMPS;l++) (p)[16*l + 2*(l>>1)] = (a)[l]; }while(0)
#define LD_B(p,a) do{ _Pragma("unroll") for(int l=0;l<AMPS;l++) (a)[l] = (p)[16*l + 2*(l>>1)]; }while(0)
#define ST_C(p,a) do{ _Pragma("unroll") for(int l=0;l<AMPS;l++) (p)[272*l] = (a)[l]; }while(0)
#define LD_C(p,a) do{ _Pragma("unroll") for(int l=0;l<AMPS;l++) (a)[l] = (p)[272*l]; }while(0)
#define ST_D(p,a) do{ _Pragma("unroll") for(int l=0;l<AMPS;l++) (p)[1088*l] = (a)[l]; }while(0)
#define LD_D(p,a) do{ _Pragma("unroll") for(int l=0;l<AMPS;l++) (a)[l] = (p)[1088*l]; }while(0)

// smem float-region offsets (after the BUFN-ull state buffer)
#define OFF_CX   0
#define OFF_SX   14
#define OFF_THT  28                         // -tan(theta/4)
#define OFF_THS  (28 + NQ*DEPTH)            // sin(theta/2)
#define OFF_RED  (OFF_THS + NQ*DEPTH)       // 196  (32 warps x 14)
#define OFF_ZF   (OFF_RED + 32*NQ)          // 644
#define N_FLOATS (OFF_ZF + NQ)              // 658
#define SMEM_BYTES ((unsigned)(BUFN * 8u) + (N_FLOATS * 4u))

__global__ void __launch_bounds__(TPB, 1)
qc_kernel(const float* __restrict__ x,
          const float* __restrict__ theta,
          const float* __restrict__ head_w,
          const float* __restrict__ head_b,
          float* __restrict__ out)
{
    extern __shared__ ull sh[];
    ull*   buf = sh;
    float* fex = (float*)(sh + BUFN);
    float* cx  = fex + OFF_CX;
    float* sx  = fex + OFF_SX;
    float* tht = fex + OFF_THT;
    float* ths = fex + OFF_THS;
    float* red = fex + OFF_RED;
    float* zf  = fex + OFF_ZF;

    const int t = threadIdx.x;
    const int b = blockIdx.x;
    const int L = t & 31, w = t >> 5;

    // ----- per-sample RX angles + shear tables -----
    if (t < NQ){
        float h = 0.5f * x[b * NQ + t];
        cx[t] = cosf(h);
        sx[t] = sinf(h);
    }
    if (t < NQ * DEPTH){
        float th = theta[t];
        tht[t] = -tanf(0.25f * th);      // -T
        ths[t] =  sinf(0.50f * th);      //  S
    }

    // ----- CZ parity masks (layouts A and D) -----
    unsigned czA = 0, czD = 0;
#pragma unroll
    for (int l = 0; l < AMPS; l++){
        int iA = (t << 4) | l;
        int iD = (l << 10) | t;
        czA |= (unsigned)(__popc(iA & (iA >> 1)) & 1) << l;
        czD |= (unsigned)(__popc(iD & (iD >> 1)) & 1) << l;
    }
    __syncthreads();

    // ----- base slot pointers (h(i) = i + 2*(i>>5)) -----
    ull* pA = buf + w*544 + L*16 + 2*(L>>1);
    ull* pB = buf + w*544 + (L>>4)*272 + (L&15);
    ull* pC = buf + (w>>3)*4096 + (w&7)*32 + L + 2*((w>>3)*128 + (w&7));
    ull* pD = buf + 34*w + L;

    // ----- initial product state, layout A -----
    // amp(i) = r(i) * (-i)^popc(i); phys bit p <-> qubit 13-p
    ull amp[AMPS];
    float rT = 1.0f;
#pragma unroll
    for (int j = 0; j < 10; j++)
        rT *= ((t >> j) & 1) ? sx[9 - j] : cx[9 - j];   // phys 4+j -> qubit 9-j
    const int kT = __popc(t);
#pragma unroll
    for (int l = 0; l < AMPS; l++){
        float r = rT;
#pragma unroll
        for (int j = 0; j < 4; j++)
            r *= ((l >> j) & 1) ? sx[13 - j] : cx[13 - j];
        int k = (kT + __popc(l)) & 3;
        float re = (k == 0) ? r : ((k == 2) ? -r : 0.0f);
        float im = (k == 1) ? -r : ((k == 3) ? r : 0.0f);
        amp[l] = pack2(re, im);
    }

#define GATE(K, IDX) do { float nt_ = tht[(IDX)], s_ = ths[(IDX)]; \
        gate<K>(amp, pack2(nt_, nt_), pack2(s_, s_)); } while (0)

    // ----- 6 layers: A -> tAB -> B -> swap -> C -> swap -> D (even), reverse (odd) -----
#pragma unroll 1
    for (int d = 0; d < DEPTH; d += 2){
        int base = d * NQ;
        // even layer
        GATE(0, base + 13); GATE(1, base + 12); GATE(2, base + 11); GATE(3, base + 10);
        ST_A(pA, amp); __syncwarp(); LD_B(pB, amp);           // intra-warp transpose
        GATE(0, base + 9);  GATE(1, base + 8);  GATE(2, base + 7);  GATE(3, base + 6);
        ST_B(pB, amp); __syncthreads(); LD_C(pC, amp);        // full swap
        GATE(0, base + 5);  GATE(1, base + 4);  GATE(2, base + 3);  GATE(3, base + 2);
        ST_C(pC, amp); __syncthreads(); LD_D(pD, amp);        // full swap
        GATE(2, base + 1);  GATE(3, base + 0);
        applyCZ(amp, czD);

        base += NQ;
        // odd layer (reverse direction)
        GATE(2, base + 1);  GATE(3, base + 0);
        ST_D(pD, amp); __syncthreads(); LD_C(pC, amp);
        GATE(0, base + 5);  GATE(1, base + 4);  GATE(2, base + 3);  GATE(3, base + 2);
        ST_C(pC, amp); __syncthreads(); LD_B(pB, amp);
        GATE(0, base + 9);  GATE(1, base + 8);  GATE(2, base + 7);  GATE(3, base + 6);
        ST_B(pB, amp); __syncwarp(); LD_A(pA, amp);           // intra-warp transpose
        GATE(0, base + 13); GATE(1, base + 12); GATE(2, base + 11); GATE(3, base + 10);
        applyCZ(amp, czA);
    }
#undef GATE

    // ----- epilogue: probs -> per-phys-bit Z expectations -> head GEMV -----
    // Layout A: i = (t<<4) | l ; phys 0-3 = l bits, phys 4-13 = t bits 0-9.
    float S = 0.0f;
    float zl0 = 0.f, zl1 = 0.f, zl2 = 0.f, zl3 = 0.f;
#pragma unroll
    for (int l = 0; l < AMPS; l++){
        float re, im; unpack2(amp[l], re, im);
        float pr = fmaf(re, re, im * im);
        S += pr;
        zl0 += (l & 1) ? -pr : pr;
        zl1 += (l & 2) ? -pr : pr;
        zl2 += (l & 4) ? -pr : pr;
        zl3 += (l & 8) ? -pr : pr;
    }
    float z[NQ];
    z[0] = zl0; z[1] = zl1; z[2] = zl2; z[3] = zl3;
#pragma unroll
    for (int j = 0; j < 10; j++)
        z[4 + j] = ((t >> j) & 1) ? -S : S;

#pragma unroll
    for (int off = 16; off; off >>= 1)
#pragma unroll
        for (int p = 0; p < NQ; p++)
            z[p] += __shfl_xor_sync(0xFFFFFFFFu, z[p], off);

    if (L == 0){
#pragma unroll
        for (int p = 0; p < NQ; p++) red[w * NQ + p] = z[p];
    }
    __syncthreads();
    if (t < NQ){
        float a = 0.0f;
#pragma unroll
        for (int ww = 0; ww < TPB / 32; ww++) a += red[ww * NQ + t];
        zf[t] = a;
    }
    __syncthreads();
    if (t < 2){
        float a = head_b[t];
#pragma unroll
        for (int p = 0; p < NQ; p++) a = fmaf(head_w[t * NQ + p], zf[p], a);
        out[b * 2 + t] = a;
    }
}

extern "C" void kernel_launch(void* const* d_in, const int* in_sizes, int n_in,
                              void* d_out, int out_size)
{
    const float* x      = (const float*)d_in[0];
    const float* theta  = (const float*)d_in[1];
    const float* head_w = (const float*)d_in[2];
    const float* head_b = (const float*)d_in[3];
    float* out = (float*)d_out;

    cudaFuncSetAttribute(qc_kernel, cudaFuncAttributeMaxDynamicSharedMemorySize, SMEM_BYTES);
    qc_kernel<<<512, TPB, SMEM_BYTES>>>(x, theta, head_w, head_b, out);
}

// round 7
// speedup vs baseline: 1.0855x; 1.0855x over previous
#include <cuda_runtime.h>

#define NQ    14
#define DEPTH 6
#define TPB   512      // 9 thread bits
#define AMPS  32       // 5 local bits

#define ROWP  33                 // padded row stride (ull): h(i) = i + (i>>5)
#define SEG   (32 * ROWP)        // 1056 ull per warp segment
#define BUFN  (16 * SEG)         // 16896 ull state buffer
#define CSTR  528                // C-layout l-stride: 512 + 16
#define CW    33                 // C-layout warp stride: 32 + 1

typedef unsigned long long ull;

// ---------- packed f32x2 helpers ----------
__device__ __forceinline__ ull pack2(float x, float y){
    ull r; asm("mov.b64 %0,{%1,%2};" : "=l"(r) : "f"(x), "f"(y)); return r;
}
__device__ __forceinline__ void unpack2(ull v, float& x, float& y){
    asm("mov.b64 {%0,%1},%2;" : "=f"(x), "=f"(y) : "l"(v));
}
__device__ __forceinline__ ull f2fma(ull a, ull b, ull c){
    ull d; asm("fma.rn.f32x2 %0,%1,%2,%3;" : "=l"(d) : "l"(a), "l"(b), "l"(c)); return d;
}

// Paeth 3-shear rotation on one pair: lo -= T*hi ; hi += S*lo ; lo -= T*hi
__device__ __forceinline__ void pairG(ull* a, int lo, int hi, ull nT, ull S){
    ull a0 = a[lo], a1 = a[hi];
    a0 = f2fma(nT, a1, a0);
    a1 = f2fma(S,  a0, a1);
    a0 = f2fma(nT, a1, a0);
    a[lo] = a0; a[hi] = a1;
}

// RY gate on register-local bit K over pair ids [m0, m1)  (m0/m1 compile-time after inline)
template<int K>
__device__ __forceinline__ void gateR(ull* a, ull nT, ull S, int m0, int m1){
#pragma unroll
    for (int m = m0; m < m1; m++){
        int lo = ((m >> K) << (K + 1)) | (m & ((1 << K) - 1));
        pairG(a, lo, lo | (1 << K), nT, S);
    }
}

// CZ chain: sign = (-1)^popc(i & (i>>1)); diagonal -> flip re/im sign bits in-register.
__device__ __forceinline__ void applyCZ(ull* amp, unsigned mask){
#pragma unroll
    for (int l = 0; l < AMPS; l++){
        if ((mask >> l) & 1u)
            amp[l] ^= 0x8000000080000000ULL;
    }
}

// smem float-region offsets (after buf + packed tables)
#define OFF_CX   0
#define OFF_SX   14
#define OFF_RED  28                 // 16 warps x 14
#define OFF_ZF   (28 + 16*NQ)       // 252
#define N_FLOATS (OFF_ZF + NQ)      // 266
#define SMEM_BYTES ((unsigned)(BUFN * 8u) + (2u * NQ * DEPTH * 8u) + (N_FLOATS * 4u))

__global__ void __launch_bounds__(TPB, 1)
qc_kernel(const float* __restrict__ x,
          const float* __restrict__ theta,
          const float* __restrict__ head_w,
          const float* __restrict__ head_b,
          float* __restrict__ out)
{
    extern __shared__ ull sh[];
    ull*   buf  = sh;                       // BUFN ull
    ull*   thtP = sh + BUFN;                // 84 packed (-T,-T)
    ull*   thsP = thtP + NQ * DEPTH;        // 84 packed ( S, S)
    float* fex  = (float*)(thsP + NQ * DEPTH);
    float* cx   = fex + OFF_CX;
    float* sx   = fex + OFF_SX;
    float* red  = fex + OFF_RED;
    float* zf   = fex + OFF_ZF;

    const int t = threadIdx.x;
    const int b = blockIdx.x;
    const int lane = t & 31, w = t >> 5;

    // ----- per-sample RX angles + packed shear tables -----
    if (t < NQ){
        float h = 0.5f * x[b * NQ + t];
        cx[t] = cosf(h);
        sx[t] = sinf(h);
    }
    if (t < NQ * DEPTH){
        float th = theta[t];
        float nt = -tanf(0.25f * th);
        float s  =  sinf(0.50f * th);
        thtP[t] = pack2(nt, nt);
        thsP[t] = pack2(s, s);
    }

    // ----- CZ parity masks (layouts A and C) -----
    unsigned czA = 0, czC = 0;
#pragma unroll
    for (int l = 0; l < AMPS; l++){
        int iA = (t << 5) | l;      // A: local = phys 0-4
        int iC = (l << 9) | t;      // C: local = phys 9-13
        czA |= (unsigned)(__popc(iA & (iA >> 1)) & 1) << l;
        czC |= (unsigned)(__popc(iC & (iC >> 1)) & 1) << l;
    }
    __syncthreads();

    // ----- slot pointers, pad h(i) = i + (i>>5) -----
    ull* tile = buf + w * SEG;
    volatile ull* vrow = tile + lane * ROWP;   // tile row store:  vrow[m]
    volatile ull* vseg = tile + lane;          // tile col / B slots: vseg[ROWP*l]
    volatile ull* vcp  = buf + CW * w + lane;  // C slots: vcp[CSTR*l]

    // ----- initial product state, layout A: i = (t<<5) | l -----
    ull amp[AMPS];
    float rT = 1.0f;
#pragma unroll
    for (int j = 0; j < 9; j++)
        rT *= ((t >> j) & 1) ? sx[8 - j] : cx[8 - j];   // phys 5+j -> qubit 8-j
    const int kT = __popc(t);
#pragma unroll
    for (int l = 0; l < AMPS; l++){
        float r = rT;
#pragma unroll
        for (int j = 0; j < 5; j++)
            r *= ((l >> j) & 1) ? sx[13 - j] : cx[13 - j];
        int k = (kT + __popc(l)) & 3;
        float re = (k == 0) ? r : ((k == 2) ? -r : 0.0f);
        float im = (k == 1) ? -r : ((k == 3) ? r : 0.0f);
        amp[l] = pack2(re, im);
    }

    // ----- 6 layers; smem ops interleaved with gate FMAs -----
#pragma unroll 1
    for (int d = 0; d < DEPTH; d += 2){
        int base = d * NQ;
        // ===== even layer: A -> tAB -> B -> swap -> C =====
        { ull nT=thtP[base+13], S=thsP[base+13]; gateR<0>(amp,nT,S,0,16); }
        { ull nT=thtP[base+12], S=thsP[base+12]; gateR<1>(amp,nT,S,0,16); }
        { ull nT=thtP[base+11], S=thsP[base+11]; gateR<2>(amp,nT,S,0,16); }
        { ull nT=thtP[base+10], S=thsP[base+10]; gateR<3>(amp,nT,S,0,16); }
        __syncwarp();   // prior col reads of tile done (cross-lane WAR)
        { ull nT=thtP[base+9], S=thsP[base+9];   // A gate<4> + tAB row stores
#pragma unroll
          for (int m = 0; m < 16; m++){
              pairG(amp, m, m+16, nT, S);
              vrow[m] = amp[m]; vrow[m+16] = amp[m+16];
          }
        }
        __syncwarp();
        // B residency: col loads woven with block gates (bits 5-7)
        { ull nT0=thtP[base+8], S0=thsP[base+8];
          ull nT1=thtP[base+7], S1=thsP[base+7];
          ull nT2=thtP[base+6], S2=thsP[base+6];
#pragma unroll
          for (int l = 0; l < 16; l++) amp[l] = vseg[ROWP*l];
          gateR<0>(amp,nT0,S0,0,4); gateR<1>(amp,nT1,S1,0,4); gateR<2>(amp,nT2,S2,0,4);
#pragma unroll
          for (int l = 16; l < 24; l++) amp[l] = vseg[ROWP*l];
          gateR<0>(amp,nT0,S0,4,8); gateR<1>(amp,nT1,S1,4,8); gateR<2>(amp,nT2,S2,4,8);
#pragma unroll
          for (int l = 24; l < 32; l++) amp[l] = vseg[ROWP*l];
          gateR<0>(amp,nT0,S0,8,12); gateR<1>(amp,nT1,S1,8,12); gateR<2>(amp,nT2,S2,8,12);
          gateR<0>(amp,nT0,S0,12,16); gateR<1>(amp,nT1,S1,12,16); gateR<2>(amp,nT2,S2,12,16);
        }
        { ull nT=thtP[base+5], S=thsP[base+5]; gateR<3>(amp,nT,S,0,16); }
        { ull nT=thtP[base+4], S=thsP[base+4];   // B gate<4> + B->C stores
#pragma unroll
          for (int m = 0; m < 16; m++){
              pairG(amp, m, m+16, nT, S);
              vseg[ROWP*m] = amp[m]; vseg[ROWP*(m+16)] = amp[m+16];
          }
        }
        __syncthreads();
        // C residency: loads woven with block gates (bits 10-11)
        { ull nT1=thtP[base+3], S1=thsP[base+3];
          ull nT2=thtP[base+2], S2=thsP[base+2];
#pragma unroll
          for (int l = 0; l < 16; l++) amp[l] = vcp[CSTR*l];
          gateR<1>(amp,nT1,S1,0,4); gateR<2>(amp,nT2,S2,0,4);
#pragma unroll
          for (int l = 16; l < 24; l++) amp[l] = vcp[CSTR*l];
          gateR<1>(amp,nT1,S1,4,8); gateR<2>(amp,nT2,S2,4,8);
#pragma unroll
          for (int l = 24; l < 32; l++) amp[l] = vcp[CSTR*l];
          gateR<1>(amp,nT1,S1,8,12); gateR<2>(amp,nT2,S2,8,12);
          gateR<1>(amp,nT1,S1,12,16); gateR<2>(amp,nT2,S2,12,16);
        }
        { ull nT=thtP[base+1], S=thsP[base+1]; gateR<3>(amp,nT,S,0,16); }
        { ull nT=thtP[base+0], S=thsP[base+0]; gateR<4>(amp,nT,S,0,16); }
        applyCZ(amp, czC);

        base += NQ;
        // ===== odd layer: C -> swap -> B -> tAB -> A =====
        { ull nT=thtP[base+4], S=thsP[base+4]; gateR<0>(amp,nT,S,0,16); }
        { ull nT=thtP[base+3], S=thsP[base+3]; gateR<1>(amp,nT,S,0,16); }
        { ull nT=thtP[base+2], S=thsP[base+2]; gateR<2>(amp,nT,S,0,16); }
        { ull nT=thtP[base+1], S=thsP[base+1]; gateR<3>(amp,nT,S,0,16); }
        { ull nT=thtP[base+0], S=thsP[base+0];   // C gate<4> + C->B stores (own slots)
#pragma unroll
          for (int m = 0; m < 16; m++){
              pairG(amp, m, m+16, nT, S);
              vcp[CSTR*m] = amp[m]; vcp[CSTR*(m+16)] = amp[m+16];
          }
        }
        __syncthreads();
        // B residency: col loads woven with block gates (bits 5-7)
        { ull nT0=thtP[base+8], S0=thsP[base+8];
          ull nT1=thtP[base+7], S1=thsP[base+7];
          ull nT2=thtP[base+6], S2=thsP[base+6];
#pragma unroll
          for (int l = 0; l < 16; l++) amp[l] = vseg[ROWP*l];
          gateR<0>(amp,nT0,S0,0,4); gateR<1>(amp,nT1,S1,0,4); gateR<2>(amp,nT2,S2,0,4);
#pragma unroll
          for (int l = 16; l < 24; l++) amp[l] = vseg[ROWP*l];
          gateR<0>(amp,nT0,S0,4,8); gateR<1>(amp,nT1,S1,4,8); gateR<2>(amp,nT2,S2,4,8);
#pragma unroll
          for (int l = 24; l < 32; l++) amp[l] = vseg[ROWP*l];
          gateR<0>(amp,nT0,S0,8,12); gateR<1>(amp,nT1,S1,8,12); gateR<2>(amp,nT2,S2,8,12);
          gateR<0>(amp,nT0,S0,12,16); gateR<1>(amp,nT1,S1,12,16); gateR<2>(amp,nT2,S2,12,16);
        }
        __syncwarp();   // cross-lane: B col loads done before tile row stores
        { ull nT=thtP[base+5], S=thsP[base+5];   // B gate<3> + tAB row stores
#pragma unroll
          for (int m = 0; m < 8; m++){
              pairG(amp, m, m+8, nT, S);
              vrow[m] = amp[m]; vrow[m+8] = amp[m+8];
          }
#pragma unroll
          for (int m = 8; m < 16; m++){
              pairG(amp, m+8, m+16, nT, S);
              vrow[m+8] = amp[m+8]; vrow[m+16] = amp[m+16];
          }
        }
        __syncwarp();
        // A residency: col loads woven with block gates (bits 0-2)
        { ull nT0=thtP[base+13], S0=thsP[base+13];
          ull nT1=thtP[base+12], S1=thsP[base+12];
          ull nT2=thtP[base+11], S2=thsP[base+11];
#pragma unroll
          for (int l = 0; l < 16; l++) amp[l] = vseg[ROWP*l];
          gateR<0>(amp,nT0,S0,0,4); gateR<1>(amp,nT1,S1,0,4); gateR<2>(amp,nT2,S2,0,4);
#pragma unroll
          for (int l = 16; l < 24; l++) amp[l] = vseg[ROWP*l];
          gateR<0>(amp,nT0,S0,4,8); gateR<1>(amp,nT1,S1,4,8); gateR<2>(amp,nT2,S2,4,8);
#pragma unroll
          for (int l = 24; l < 32; l++) amp[l] = vseg[ROWP*l];
          gateR<0>(amp,nT0,S0,8,12); gateR<1>(amp,nT1,S1,8,12); gateR<2>(amp,nT2,S2,8,12);
          gateR<0>(amp,nT0,S0,12,16); gateR<1>(amp,nT1,S1,12,16); gateR<2>(amp,nT2,S2,12,16);
        }
        { ull nT=thtP[base+10], S=thsP[base+10]; gateR<3>(amp,nT,S,0,16); }
        { ull nT=thtP[base+9],  S=thsP[base+9];  gateR<4>(amp,nT,S,0,16); }
        applyCZ(amp, czA);
    }

    // ----- epilogue: probs -> per-bit Z expectations -> head GEMV (layout A) -----
    float S = 0.0f;
    float zl0 = 0.f, zl1 = 0.f, zl2 = 0.f, zl3 = 0.f, zl4 = 0.f;
#pragma unroll
    for (int l = 0; l < AMPS; l++){
        float re, im; unpack2(amp[l], re, im);
        float pr = fmaf(re, re, im * im);
        S += pr;
        zl0 += (l & 1)  ? -pr : pr;
        zl1 += (l & 2)  ? -pr : pr;
        zl2 += (l & 4)  ? -pr : pr;
        zl3 += (l & 8)  ? -pr : pr;
        zl4 += (l & 16) ? -pr : pr;
    }
    float z[NQ];
    z[0] = zl0; z[1] = zl1; z[2] = zl2; z[3] = zl3; z[4] = zl4;
#pragma unroll
    for (int j = 0; j < 9; j++)
        z[5 + j] = ((t >> j) & 1) ? -S : S;

#pragma unroll
    for (int off = 16; off; off >>= 1)
#pragma unroll
        for (int p = 0; p < NQ; p++)
            z[p] += __shfl_xor_sync(0xFFFFFFFFu, z[p], off);

    if (lane == 0){
#pragma unroll
        for (int p = 0; p < NQ; p++) red[w * NQ + p] = z[p];
    }
    __syncthreads();
    if (t < NQ){
        float a = 0.0f;
#pragma unroll
        for (int ww = 0; ww < TPB / 32; ww++) a += red[ww * NQ + t];
        zf[t] = a;
    }
    __syncthreads();
    if (t < 2){
        float a = head_b[t];
#pragma unroll
        for (int p = 0; p < NQ; p++) a = fmaf(head_w[t * NQ + p], zf[p], a);
        out[b * 2 + t] = a;
    }
}

extern "C" void kernel_launch(void* const* d_in, const int* in_sizes, int n_in,
                              void* d_out, int out_size)
{
    const float* x      = (const float*)d_in[0];
    const float* theta  = (const float*)d_in[1];
    const float* head_w = (const float*)d_in[2];
    const float* head_b = (const float*)d_in[3];
    float* out = (float*)d_out;

    cudaFuncSetAttribute(qc_kernel, cudaFuncAttributeMaxDynamicSharedMemorySize, SMEM_BYTES);
    qc_kernel<<<512, TPB, SMEM_BYTES>>>(x, theta, head_w, head_b, out);
}

// round 8
// speedup vs baseline: 1.0919x; 1.0059x over previous
#include <cuda_runtime.h>

#define NQ    14
#define DEPTH 6
#define TPB   512      // 9 thread bits
#define AMPS  32       // 5 local bits

#define ROWP  33                 // padded row stride (ull): h(i) = i + (i>>5)
#define SEG   (32 * ROWP)        // 1056 ull per warp segment
#define BUFN  (16 * SEG)         // 16896 ull state buffer
#define CSTR  528                // C-layout l-stride: 512 + 16
#define CW    33                 // C-layout warp stride: 32 + 1

typedef unsigned long long ull;

// ---------- packed f32x2 helpers ----------
__device__ __forceinline__ ull pack2(float x, float y){
    ull r; asm("mov.b64 %0,{%1,%2};" : "=l"(r) : "f"(x), "f"(y)); return r;
}
__device__ __forceinline__ void unpack2(ull v, float& x, float& y){
    asm("mov.b64 {%0,%1},%2;" : "=f"(x), "=f"(y) : "l"(v));
}
__device__ __forceinline__ ull f2fma(ull a, ull b, ull c){
    ull d; asm("fma.rn.f32x2 %0,%1,%2,%3;" : "=l"(d) : "l"(a), "l"(b), "l"(c)); return d;
}

// Paeth 3-shear rotation on one pair: lo -= T*hi ; hi += S*lo ; lo -= T*hi
__device__ __forceinline__ void pairG(ull* a, int lo, int hi, ull nT, ull S){
    ull a0 = a[lo], a1 = a[hi];
    a0 = f2fma(nT, a1, a0);
    a1 = f2fma(S,  a0, a1);
    a0 = f2fma(nT, a1, a0);
    a[lo] = a0; a[hi] = a1;
}

// RY gate on register-local bit K over pair ids [m0, m1)  (m0/m1 compile-time after inline)
template<int K>
__device__ __forceinline__ void gateR(ull* a, ull nT, ull S, int m0, int m1){
#pragma unroll
    for (int m = m0; m < m1; m++){
        int lo = ((m >> K) << (K + 1)) | (m & ((1 << K) - 1));
        pairG(a, lo, lo | (1 << K), nT, S);
    }
}

// CZ chain: sign = (-1)^popc(i & (i>>1)); diagonal -> flip re/im sign bits in-register.
__device__ __forceinline__ void applyCZ(ull* amp, unsigned mask){
#pragma unroll
    for (int l = 0; l < AMPS; l++){
        if ((mask >> l) & 1u)
            amp[l] ^= 0x8000000080000000ULL;
    }
}

// smem float-region offsets (after buf + packed tables)
#define OFF_CX   0
#define OFF_SX   14
#define OFF_RED  28                 // 16 warps x 14
#define OFF_ZF   (28 + 16*NQ)       // 252
#define N_FLOATS (OFF_ZF + NQ)      // 266
#define SMEM_BYTES ((unsigned)(BUFN * 8u) + (2u * NQ * DEPTH * 8u) + (N_FLOATS * 4u))

__global__ void __launch_bounds__(TPB, 1)
qc_kernel(const float* __restrict__ x,
          const float* __restrict__ theta,
          const float* __restrict__ head_w,
          const float* __restrict__ head_b,
          float* __restrict__ out)
{
    extern __shared__ ull sh[];
    ull*   buf  = sh;                       // BUFN ull
    ull*   thtP = sh + BUFN;                // 84 packed (-T,-T)
    ull*   thsP = thtP + NQ * DEPTH;        // 84 packed ( S, S)
    float* fex  = (float*)(thsP + NQ * DEPTH);
    float* cx   = fex + OFF_CX;
    float* sx   = fex + OFF_SX;
    float* red  = fex + OFF_RED;
    float* zf   = fex + OFF_ZF;

    const int t = threadIdx.x;
    const int b = blockIdx.x;
    const int lane = t & 31, w = t >> 5;

    // ----- per-sample RX angles + packed shear tables -----
    if (t < NQ){
        float h = 0.5f * x[b * NQ + t];
        cx[t] = cosf(h);
        sx[t] = sinf(h);
    }
    if (t < NQ * DEPTH){
        float th = theta[t];
        float nt = -tanf(0.25f * th);
        float s  =  sinf(0.50f * th);
        thtP[t] = pack2(nt, nt);
        thsP[t] = pack2(s, s);
    }

    // ----- CZ parity masks (layouts A and C) -----
    unsigned czA = 0, czC = 0;
#pragma unroll
    for (int l = 0; l < AMPS; l++){
        int iA = (t << 5) | l;      // A: local = phys 0-4
        int iC = (l << 9) | t;      // C: local = phys 9-13
        czA |= (unsigned)(__popc(iA & (iA >> 1)) & 1) << l;
        czC |= (unsigned)(__popc(iC & (iC >> 1)) & 1) << l;
    }
    __syncthreads();

    // ----- slot pointers, pad h(i) = i + (i>>5) -----
    ull* tile = buf + w * SEG;
    volatile ull* vrow = tile + lane * ROWP;   // tile row store:  vrow[m]
    volatile ull* vseg = tile + lane;          // tile col / B slots: vseg[ROWP*l]
    volatile ull* vcp  = buf + CW * w + lane;  // C slots: vcp[CSTR*l]

    // ----- initial product state, layout A: i = (t<<5) | l -----
    ull amp[AMPS];
    float rT = 1.0f;
#pragma unroll
    for (int j = 0; j < 9; j++)
        rT *= ((t >> j) & 1) ? sx[8 - j] : cx[8 - j];   // phys 5+j -> qubit 8-j
    const int kT = __popc(t);
#pragma unroll
    for (int l = 0; l < AMPS; l++){
        float r = rT;
#pragma unroll
        for (int j = 0; j < 5; j++)
            r *= ((l >> j) & 1) ? sx[13 - j] : cx[13 - j];
        int k = (kT + __popc(l)) & 3;
        float re = (k == 0) ? r : ((k == 2) ? -r : 0.0f);
        float im = (k == 1) ? -r : ((k == 3) ? r : 0.0f);
        amp[l] = pack2(re, im);
    }

    // ----- 6 layers; smem ops interleaved with gate FMAs -----
#pragma unroll 1
    for (int d = 0; d < DEPTH; d += 2){
        int base = d * NQ;
        // ===== even layer: A -> tAB -> B -> swap -> C =====
        { ull nT=thtP[base+13], S=thsP[base+13]; gateR<0>(amp,nT,S,0,16); }
        { ull nT=thtP[base+12], S=thsP[base+12]; gateR<1>(amp,nT,S,0,16); }
        { ull nT=thtP[base+11], S=thsP[base+11]; gateR<2>(amp,nT,S,0,16); }
        { ull nT=thtP[base+10], S=thsP[base+10]; gateR<3>(amp,nT,S,0,16); }
        __syncwarp();   // prior col reads of tile done (cross-lane WAR)
        { ull nT=thtP[base+9], S=thsP[base+9];   // A gate<4> + tAB row stores
#pragma unroll
          for (int m = 0; m < 16; m++){
              pairG(amp, m, m+16, nT, S);
              vrow[m] = amp[m]; vrow[m+16] = amp[m+16];
          }
        }
        __syncwarp();
        // B residency: col loads woven with block gates (bits 5-7)
        { ull nT0=thtP[base+8], S0=thsP[base+8];
          ull nT1=thtP[base+7], S1=thsP[base+7];
          ull nT2=thtP[base+6], S2=thsP[base+6];
#pragma unroll
          for (int l = 0; l < 16; l++) amp[l] = vseg[ROWP*l];
          gateR<0>(amp,nT0,S0,0,4); gateR<1>(amp,nT1,S1,0,4); gateR<2>(amp,nT2,S2,0,4);
#pragma unroll
          for (int l = 16; l < 24; l++) amp[l] = vseg[ROWP*l];
          gateR<0>(amp,nT0,S0,4,8); gateR<1>(amp,nT1,S1,4,8); gateR<2>(amp,nT2,S2,4,8);
#pragma unroll
          for (int l = 24; l < 32; l++) amp[l] = vseg[ROWP*l];
          gateR<0>(amp,nT0,S0,8,12); gateR<1>(amp,nT1,S1,8,12); gateR<2>(amp,nT2,S2,8,12);
          gateR<0>(amp,nT0,S0,12,16); gateR<1>(amp,nT1,S1,12,16); gateR<2>(amp,nT2,S2,12,16);
        }
        { ull nT=thtP[base+5], S=thsP[base+5]; gateR<3>(amp,nT,S,0,16); }
        { ull nT=thtP[base+4], S=thsP[base+4];   // B gate<4> + B->C stores
#pragma unroll
          for (int m = 0; m < 16; m++){
              pairG(amp, m, m+16, nT, S);
              vseg[ROWP*m] = amp[m]; vseg[ROWP*(m+16)] = amp[m+16];
          }
        }
        __syncthreads();
        // C residency: loads woven with block gates (bits 10-11)
        { ull nT1=thtP[base+3], S1=thsP[base+3];
          ull nT2=thtP[base+2], S2=thsP[base+2];
#pragma unroll
          for (int l = 0; l < 16; l++) amp[l] = vcp[CSTR*l];
          gateR<1>(amp,nT1,S1,0,4); gateR<2>(amp,nT2,S2,0,4);
#pragma unroll
          for (int l = 16; l < 24; l++) amp[l] = vcp[CSTR*l];
          gateR<1>(amp,nT1,S1,4,8); gateR<2>(amp,nT2,S2,4,8);
#pragma unroll
          for (int l = 24; l < 32; l++) amp[l] = vcp[CSTR*l];
          gateR<1>(amp,nT1,S1,8,12); gateR<2>(amp,nT2,S2,8,12);
          gateR<1>(amp,nT1,S1,12,16); gateR<2>(amp,nT2,S2,12,16);
        }
        { ull nT=thtP[base+1], S=thsP[base+1]; gateR<3>(amp,nT,S,0,16); }
        { ull nT=thtP[base+0], S=thsP[base+0]; gateR<4>(amp,nT,S,0,16); }
        applyCZ(amp, czC);

        base += NQ;
        // ===== odd layer: C -> swap -> B -> tAB -> A =====
        { ull nT=thtP[base+4], S=thsP[base+4]; gateR<0>(amp,nT,S,0,16); }
        { ull nT=thtP[base+3], S=thsP[base+3]; gateR<1>(amp,nT,S,0,16); }
        { ull nT=thtP[base+2], S=thsP[base+2]; gateR<2>(amp,nT,S,0,16); }
        { ull nT=thtP[base+1], S=thsP[base+1]; gateR<3>(amp,nT,S,0,16); }
        { ull nT=thtP[base+0], S=thsP[base+0];   // C gate<4> + C->B stores (own slots)
#pragma unroll
          for (int m = 0; m < 16; m++){
              pairG(amp, m, m+16, nT, S);
              vcp[CSTR*m] = amp[m]; vcp[CSTR*(m+16)] = amp[m+16];
          }
        }
        __syncthreads();
        // B residency: col loads woven with block gates (bits 5-7)
        { ull nT0=thtP[base+8], S0=thsP[base+8];
          ull nT1=thtP[base+7], S1=thsP[base+7];
          ull nT2=thtP[base+6], S2=thsP[base+6];
#pragma unroll
          for (int l = 0; l < 16; l++) amp[l] = vseg[ROWP*l];
          gateR<0>(amp,nT0,S0,0,4); gateR<1>(amp,nT1,S1,0,4); gateR<2>(amp,nT2,S2,0,4);
#pragma unroll
          for (int l = 16; l < 24; l++) amp[l] = vseg[ROWP*l];
          gateR<0>(amp,nT0,S0,4,8); gateR<1>(amp,nT1,S1,4,8); gateR<2>(amp,nT2,S2,4,8);
#pragma unroll
          for (int l = 24; l < 32; l++) amp[l] = vseg[ROWP*l];
          gateR<0>(amp,nT0,S0,8,12); gateR<1>(amp,nT1,S1,8,12); gateR<2>(amp,nT2,S2,8,12);
          gateR<0>(amp,nT0,S0,12,16); gateR<1>(amp,nT1,S1,12,16); gateR<2>(amp,nT2,S2,12,16);
        }
        __syncwarp();   // cross-lane: B col loads done before tile row stores
        { ull nT=thtP[base+5], S=thsP[base+5];   // B gate<3> + tAB row stores
#pragma unroll
          for (int m = 0; m < 8; m++){
              pairG(amp, m, m+8, nT, S);
              vrow[m] = amp[m]; vrow[m+8] = amp[m+8];
          }
#pragma unroll
          for (int m = 8; m < 16; m++){
              pairG(amp, m+8, m+16, nT, S);
              vrow[m+8] = amp[m+8]; vrow[m+16] = amp[m+16];
          }
        }
        __syncwarp();
        // A residency: col loads woven with block gates (bits 0-2)
        { ull nT0=thtP[base+13], S0=thsP[base+13];
          ull nT1=thtP[base+12], S1=thsP[base+12];
          ull nT2=thtP[base+11], S2=thsP[base+11];
#pragma unroll
          for (int l = 0; l < 16; l++) amp[l] = vseg[ROWP*l];
          gateR<0>(amp,nT0,S0,0,4); gateR<1>(amp,nT1,S1,0,4); gateR<2>(amp,nT2,S2,0,4);
#pragma unroll
          for (int l = 16; l < 24; l++) amp[l] = vseg[ROWP*l];
          gateR<0>(amp,nT0,S0,4,8); gateR<1>(amp,nT1,S1,4,8); gateR<2>(amp,nT2,S2,4,8);
#pragma unroll
          for (int l = 24; l < 32; l++) amp[l] = vseg[ROWP*l];
          gateR<0>(amp,nT0,S0,8,12); gateR<1>(amp,nT1,S1,8,12); gateR<2>(amp,nT2,S2,8,12);
          gateR<0>(amp,nT0,S0,12,16); gateR<1>(amp,nT1,S1,12,16); gateR<2>(amp,nT2,S2,12,16);
        }
        { ull nT=thtP[base+10], S=thsP[base+10]; gateR<3>(amp,nT,S,0,16); }
        { ull nT=thtP[base+9],  S=thsP[base+9];  gateR<4>(amp,nT,S,0,16); }
        applyCZ(amp, czA);
    }

    // ----- epilogue: probs -> per-bit Z expectations -> head GEMV (layout A) -----
    float S = 0.0f;
    float zl0 = 0.f, zl1 = 0.f, zl2 = 0.f, zl3 = 0.f, zl4 = 0.f;
#pragma unroll
    for (int l = 0; l < AMPS; l++){
        float re, im; unpack2(amp[l], re, im);
        float pr = fmaf(re, re, im * im);
        S += pr;
        zl0 += (l & 1)  ? -pr : pr;
        zl1 += (l & 2)  ? -pr : pr;
        zl2 += (l & 4)  ? -pr : pr;
        zl3 += (l & 8)  ? -pr : pr;
        zl4 += (l & 16) ? -pr : pr;
    }
    float z[NQ];
    z[0] = zl0; z[1] = zl1; z[2] = zl2; z[3] = zl3; z[4] = zl4;
#pragma unroll
    for (int j = 0; j < 9; j++)
        z[5 + j] = ((t >> j) & 1) ? -S : S;

#pragma unroll
    for (int off = 16; off; off >>= 1)
#pragma unroll
        for (int p = 0; p < NQ; p++)
            z[p] += __shfl_xor_sync(0xFFFFFFFFu, z[p], off);

    if (lane == 0){
#pragma unroll
        for (int p = 0; p < NQ; p++) red[w * NQ + p] = z[p];
    }
    __syncthreads();
    if (t < NQ){
        float a = 0.0f;
#pragma unroll
        for (int ww = 0; ww < TPB / 32; ww++) a += red[ww * NQ + t];
        zf[t] = a;
    }
    __syncthreads();
    if (t < 2){
        float a = head_b[t];
#pragma unroll
        for (int p = 0; p < NQ; p++) a = fmaf(head_w[t * NQ + p], zf[p], a);
        out[b * 2 + t] = a;
    }
}

extern "C" void kernel_launch(void* const* d_in, const int* in_sizes, int n_in,
                              void* d_out, int out_size)
{
    const float* x      = (const float*)d_in[0];
    const float* theta  = (const float*)d_in[1];
    const float* head_w = (const float*)d_in[2];
    const float* head_b = (const float*)d_in[3];
    float* out = (float*)d_out;

    cudaFuncSetAttribute(qc_kernel, cudaFuncAttributeMaxDynamicSharedMemorySize, SMEM_BYTES);
    qc_kernel<<<512, TPB, SMEM_BYTES>>>(x, theta, head_w, head_b, out);
}

// round 9
// speedup vs baseline: 1.4649x; 1.3415x over previous
#include <cuda_runtime.h>

#define NQ    14
#define DEPTH 6
#define TPB   512      // 9 thread bits
#define AMPS  32       // 5 local bits

#define ROWP  34                 // padded row stride (ull): h(i) = i + 2*(i>>5)
#define SEG   (32 * ROWP)        // 1088 ull per warp segment
#define BUFN  (16 * SEG)         // 17408 ull state buffer
#define SGNM  0x8000000080000000ULL

typedef unsigned long long ull;

// ---------- packed f32x2 helpers ----------
__device__ __forceinline__ ull pack2(float x, float y){
    ull r; asm("mov.b64 %0,{%1,%2};" : "=l"(r) : "f"(x), "f"(y)); return r;
}
__device__ __forceinline__ void unpack2(ull v, float& x, float& y){
    asm("mov.b64 {%0,%1},%2;" : "=f"(x), "=f"(y) : "l"(v));
}
__device__ __forceinline__ ull f2mul(ull a, ull b){
    ull d; asm("mul.rn.f32x2 %0,%1,%2;" : "=l"(d) : "l"(a), "l"(b)); return d;
}
__device__ __forceinline__ ull f2fma(ull a, ull b, ull c){
    ull d; asm("fma.rn.f32x2 %0,%1,%2,%3;" : "=l"(d) : "l"(a), "l"(b), "l"(c)); return d;
}

// complex multiply: (re,im packed) * (ur + i*ui)
__device__ __forceinline__ ull cmul(ull av, float ur, float ui){
    float xx, yy; unpack2(av, xx, yy);
    ull t1 = f2mul(pack2(ur, ur), av);
    return f2fma(pack2(-ui, ui), pack2(yy, xx), t1);
}

// Paeth 3-shear rotation on one pair: lo -= T*hi ; hi += S*lo ; lo -= T*hi
__device__ __forceinline__ void pairG(ull* a, int lo, int hi, ull nT, ull S){
    ull a0 = a[lo], a1 = a[hi];
    a0 = f2fma(nT, a1, a0);
    a1 = f2fma(S,  a0, a1);
    a0 = f2fma(nT, a1, a0);
    a[lo] = a0; a[hi] = a1;
}

// Plain RY gate on register-local bit K (all 16 pairs)
template<int K>
__device__ __forceinline__ void gate(ull* a, ull nT, ull S){
#pragma unroll
    for (int m = 0; m < 16; m++){
        int lo = ((m >> K) << (K + 1)) | (m & ((1 << K) - 1));
        pairG(a, lo, lo | (1 << K), nT, S);
    }
}

// Merged gate: M = RY(beta)*diag(1,r)*RY(alpha) per pair, r = (-1)^(neighbor bits).
// NBM = mask of LOCAL bits contributing to r (compile-time per pair); tp = thread part.
// flip = lp ^ tp : flip==0 -> rotation by (a+b)/2 (sum coeffs);
//                  flip==1 -> a1 sign-flip, then rotation by (b-a)/2 (diff coeffs).
template<int K, int NBM>
__device__ __forceinline__ void mgate(ull* a, ull sT, ull sS, ull dT, ull dS, int tp){
    ull cT0 = tp ? dT : sT, cS0 = tp ? dS : sS;       // lp = 0
    ull cT1 = tp ? sT : dT, cS1 = tp ? sS : dS;       // lp = 1
    ull F0  = tp ? SGNM : 0ULL;
    ull F1  = F0 ^ SGNM;
#pragma unroll
    for (int m = 0; m < 16; m++){
        int lo = ((m >> K) << (K + 1)) | (m & ((1 << K) - 1));
        int hi = lo | (1 << K);
        int lp = __popc(lo & NBM) & 1;                // compile-time
        if (lp){ a[hi] ^= F1; pairG(a, lo, hi, cT1, cS1); }
        else   { a[hi] ^= F0; pairG(a, lo, hi, cT0, cS0); }
    }
}

// CZ chain mask apply (diagonal sign flips)
__device__ __forceinline__ void applyCZ(ull* amp, unsigned mask){
#pragma unroll
    for (int l = 0; l < AMPS; l++){
        if ((mask >> l) & 1u) amp[l] ^= SGNM;
    }
}

// ---------- exchanges (verbatim from the 143.4us kernel) ----------
__device__ __forceinline__ void transposeAB(ull* buf, ull* amp, int t){
    ull* tile = buf + (t >> 5) * SEG;
    const int lane = t & 31;
    __syncwarp();
#pragma unroll
    for (int l = 0; l < AMPS; l += 2){
        ulonglong2 v; v.x = amp[l]; v.y = amp[l + 1];
        *reinterpret_cast<ulonglong2*>(tile + lane * ROWP + l) = v;
    }
    __syncwarp();
#pragma unroll
    for (int l = 0; l < AMPS; l++)
        amp[l] = tile[l * ROWP + lane];
}

__device__ __forceinline__ void swapBtoC(ull* buf, ull* amp, int t){
    const int lane = t & 31, w = t >> 5;
    ull* segp = buf + SEG * w + lane;
    __syncwarp();
#pragma unroll
    for (int l = 0; l < AMPS; l++) segp[ROWP * l] = amp[l];
    __syncthreads();
    ull* cp = buf + 34 * w + lane;
#pragma unroll
    for (int l = 0; l < AMPS; l++) amp[l] = cp[544 * l];
}

__device__ __forceinline__ void swapCtoB(ull* buf, ull* amp, int t){
    const int lane = t & 31, w = t >> 5;
    ull* cp = buf + 34 * w + lane;
#pragma unroll
    for (int l = 0; l < AMPS; l++) cp[544 * l] = amp[l];   // own slots (no lead barrier needed)
    __syncthreads();
    ull* segp = buf + SEG * w + lane;
#pragma unroll
    for (int l = 0; l < AMPS; l++) amp[l] = segp[ROWP * l];
}

// ---------- smem layout ----------
#define TABN   84
#define OFF_U0R 0
#define OFF_U0I 14
#define OFF_U1R 28
#define OFF_U1I 42
#define OFF_RED 56                   // 16 warps x 14
#define OFF_ZF  (56 + 16*NQ)         // 280
#define N_FLOATS (OFF_ZF + NQ)       // 294
#define SMEM_BYTES ((unsigned)((BUFN + 4*TABN) * 8u) + (N_FLOATS * 4u))

__global__ void __launch_bounds__(TPB, 1)
qc_kernel(const float* __restrict__ x,
          const float* __restrict__ theta,
          const float* __restrict__ head_w,
          const float* __restrict__ head_b,
          float* __restrict__ out)
{
    extern __shared__ ull sh[];
    ull*   buf  = sh;
    ull*   sumT = sh + BUFN;
    ull*   sumS = sumT + TABN;
    ull*   difT = sumS + TABN;
    ull*   difS = difT + TABN;
    float* fex  = (float*)(difS + TABN);
    float* u0r  = fex + OFF_U0R;
    float* u0i  = fex + OFF_U0I;
    float* u1r  = fex + OFF_U1R;
    float* u1i  = fex + OFF_U1I;
    float* red  = fex + OFF_RED;
    float* zf   = fex + OFF_ZF;

    const int t = threadIdx.x;
    const int b = blockIdx.x;
    const int lane = t & 31, w = t >> 5;

    // ----- per-qubit init vectors: u_p = RY(theta_L0)*RX(x)|0>, p = phys bit, q=13-p -----
    if (t < NQ){
        int p = t, q = 13 - p;
        float h  = 0.5f * x[b * NQ + q];
        float c  = cosf(h), s = sinf(h);
        float A0 = 0.5f * theta[q];               // layer 0
        float ca = cosf(A0), sa = sinf(A0);
        u0r[p] = ca * c;  u0i[p] = sa * s;        // v0 = ca*c + i*sa*s
        u1r[p] = sa * c;  u1i[p] = -ca * s;       // v1 = sa*c - i*ca*s
    }
    // ----- stage coefficient tables: idx = s*14 + p -----
    if (t < TABN){
        int s = t / NQ, p = t % NQ, q = 13 - p;
        float sum, dif;
        if (s == 0){ sum = theta[NQ + q];      dif = 0.f; }        // plain RY layer1
        else if (s == 5){ sum = theta[5*NQ + q]; dif = 0.f; }      // plain RY layer5
        else { float a = theta[s*NQ + q], bb = theta[(s+1)*NQ + q]; sum = a + bb; dif = bb - a; }
        float st = -tanf(0.25f * sum), ss = sinf(0.5f * sum);
        float dt = -tanf(0.25f * dif), ds = sinf(0.5f * dif);
        sumT[t] = pack2(st, st); sumS[t] = pack2(ss, ss);
        difT[t] = pack2(dt, dt); difS[t] = pack2(ds, ds);
    }
    // ----- CZ parity mask (layout A) -----
    unsigned czA = 0;
#pragma unroll
    for (int l = 0; l < AMPS; l++){
        int iA = (t << 5) | l;
        czA |= (unsigned)(__popc(iA & (iA >> 1)) & 1) << l;
    }
    __syncthreads();

    // ----- initial product state (layer 0 folded), layout A: i = (t<<5)|l -----
    ull amp[AMPS];
    {
        float rre = 1.f, rim = 0.f;
#pragma unroll
        for (int j = 0; j < 9; j++){
            int p = 5 + j, bb = (t >> j) & 1;
            float ur = bb ? u1r[p] : u0r[p];
            float ui = bb ? u1i[p] : u0i[p];
            float nr = rre * ur - rim * ui;
            float ni = rre * ui + rim * ur;
            rre = nr; rim = ni;
        }
        amp[0] = pack2(rre, rim);
#pragma unroll
        for (int j = 0; j < 5; j++){
            float a0r = u0r[j], a0i = u0i[j], a1r = u1r[j], a1i = u1i[j];
#pragma unroll
            for (int l = 0; l < (1 << j); l++){
                amp[l | (1 << j)] = cmul(amp[l], a1r, a1i);
                amp[l]            = cmul(amp[l], a0r, a0i);
            }
        }
    }
    applyCZ(amp, czA);   // CZ after layer 0

#define PG(K, s, p) do { ull T_=sumT[(s)*14+(p)], S_=sumS[(s)*14+(p)]; gate<K>(amp, T_, S_); } while (0)
#define MG(K, NBM, s, p, TP) do { int tp_=(TP); \
        ull sT_=sumT[(s)*14+(p)], sS_=sumS[(s)*14+(p)]; \
        ull dT_=difT[(s)*14+(p)], dS_=difS[(s)*14+(p)]; \
        mgate<K, NBM>(amp, sT_, sS_, dT_, dS_, tp_); } while (0)

    // ===== S1: plain RY layer1, even phys (A -> B -> C) =====
    PG(0,0,0); PG(2,0,2); PG(4,0,4);
    transposeAB(buf, amp, t);
    PG(1,0,6); PG(3,0,8);
    swapBtoC(buf, amp, t);
    PG(1,0,10); PG(3,0,12);
    // ===== S2: merged L1+CZ1+L2, odd phys (C -> B -> A) =====
    MG(0, 0b00010, 1, 9, (t>>8)&1); MG(2, 0b01010, 1, 11, 0); MG(4, 0b01000, 1, 13, 0);
    swapCtoB(buf, amp, t);
    MG(0, 0b00010, 1, 5, (t>>4)&1); MG(2, 0b01010, 1, 7, 0);
    transposeAB(buf, amp, t);
    MG(1, 0b00101, 1, 1, 0); MG(3, 0b10100, 1, 3, 0);
    // ===== S3: merged L2+CZ2+L3, even phys (A -> B -> C) =====
    MG(0, 0b00010, 2, 0, 0); MG(2, 0b01010, 2, 2, 0); MG(4, 0b01000, 2, 4, t&1);
    transposeAB(buf, amp, t);
    MG(1, 0b00101, 2, 6, 0); MG(3, 0b10100, 2, 8, 0);
    swapBtoC(buf, amp, t);
    MG(1, 0b00101, 2, 10, 0); MG(3, 0b10100, 2, 12, 0);
    // ===== S4: merged L3+CZ3+L4, odd phys (C -> B -> A) =====
    MG(0, 0b00010, 3, 9, (t>>8)&1); MG(2, 0b01010, 3, 11, 0); MG(4, 0b01000, 3, 13, 0);
    swapCtoB(buf, amp, t);
    MG(0, 0b00010, 3, 5, (t>>4)&1); MG(2, 0b01010, 3, 7, 0);
    transposeAB(buf, amp, t);
    MG(1, 0b00101, 3, 1, 0); MG(3, 0b10100, 3, 3, 0);
    // ===== S5: merged L4+CZ4+L5, even phys (A -> B -> C) =====
    MG(0, 0b00010, 4, 0, 0); MG(2, 0b01010, 4, 2, 0); MG(4, 0b01000, 4, 4, t&1);
    transposeAB(buf, amp, t);
    MG(1, 0b00101, 4, 6, 0); MG(3, 0b10100, 4, 8, 0);
    swapBtoC(buf, amp, t);
    MG(1, 0b00101, 4, 10, 0); MG(3, 0b10100, 4, 12, 0);
    // ===== S6: plain RY layer5, odd phys (C -> B -> A) =====
    PG(0,5,9); PG(2,5,11); PG(4,5,13);
    swapCtoB(buf, amp, t);
    PG(0,5,5); PG(2,5,7);
    transposeAB(buf, amp, t);
    PG(1,5,1); PG(3,5,3);
    applyCZ(amp, czA);   // final CZ

#undef PG
#undef MG

    // ----- epilogue: probs -> per-bit Z expectations -> head GEMV (layout A) -----
    float S = 0.0f;
    float zl0 = 0.f, zl1 = 0.f, zl2 = 0.f, zl3 = 0.f, zl4 = 0.f;
#pragma unroll
    for (int l = 0; l < AMPS; l++){
        float re, im; unpack2(amp[l], re, im);
        float pr = fmaf(re, re, im * im);
        S += pr;
        zl0 += (l & 1)  ? -pr : pr;
        zl1 += (l & 2)  ? -pr : pr;
        zl2 += (l & 4)  ? -pr : pr;
        zl3 += (l & 8)  ? -pr : pr;
        zl4 += (l & 16) ? -pr : pr;
    }
    float z[NQ];
    z[0] = zl0; z[1] = zl1; z[2] = zl2; z[3] = zl3; z[4] = zl4;
#pragma unroll
    for (int j = 0; j < 9; j++)
        z[5 + j] = ((t >> j) & 1) ? -S : S;

#pragma unroll
    for (int off = 16; off; off >>= 1)
#pragma unroll
        for (int p = 0; p < NQ; p++)
            z[p] += __shfl_xor_sync(0xFFFFFFFFu, z[p], off);

    if (lane == 0){
#pragma unroll
        for (int p = 0; p < NQ; p++) red[w * NQ + p] = z[p];
    }
    __syncthreads();
    if (t < NQ){
        float a = 0.0f;
#pragma unroll
        for (int ww = 0; ww < TPB / 32; ww++) a += red[ww * NQ + t];
        zf[t] = a;
    }
    __syncthreads();
    if (t < 2){
        float a = head_b[t];
#pragma unroll
        for (int p = 0; p < NQ; p++) a = fmaf(head_w[t * NQ + p], zf[p], a);
        out[b * 2 + t] = a;
    }
}

extern "C" void kernel_launch(void* const* d_in, const int* in_sizes, int n_in,
                              void* d_out, int out_size)
{
    const float* x      = (const float*)d_in[0];
    const float* theta  = (const float*)d_in[1];
    const float* head_w = (const float*)d_in[2];
    const float* head_b = (const float*)d_in[3];
    float* out = (float*)d_out;

    cudaFuncSetAttribute(qc_kernel, cudaFuncAttributeMaxDynamicSharedMemorySize, SMEM_BYTES);
    qc_kernel<<<512, TPB, SMEM_BYTES>>>(x, theta, head_w, head_b, out);
}